// round 17
// baseline (speedup 1.0000x reference)
#include <cuda_runtime.h>
#include <cuda_fp16.h>
#include <cstdint>
#include <math.h>

#define BB 4
#define SS 4096
#define DD 2048
#define HH 16
#define HDIM 128
#define NKEYS 128

// ---------------- scratch ----------------
__device__ __half g_qh [(size_t)BB * SS * DD];   // Q, attn-smem image
__device__ __half g_att[(size_t)BB * SS * DD];   // half TILED (GEMM2 A)
__device__ __half g_xh [(size_t)BB * SS * DD];   // half TILED
__device__ __half g_wqt[2048 * 2048];            // half TILED [n][k]
__device__ __half g_wot[2048 * 2048];
__device__ __half g_wkt[2048 * 2048];
__device__ __half g_wvt[2048 * 2048];
__device__ __half g_kh [64 * NKEYS * HDIM];      // K attn image
__device__ __half g_vh [64 * NKEYS * HDIM];      // V attn image (transposed)

// ---------------- helpers ----------------
__device__ __forceinline__ uint32_t smem_u32(const void* p) {
    uint32_t a;
    asm("{ .reg .u64 t; cvta.to.shared.u64 t, %1; cvt.u32.u64 %0, t; }" : "=r"(a) : "l"(p));
    return a;
}
#define CP_ASYNC16(dst, src) \
    asm volatile("cp.async.cg.shared.global [%0], [%1], 16;" :: "r"(dst), "l"(src) : "memory")
#define CP_COMMIT() asm volatile("cp.async.commit_group;" ::: "memory")
#define CP_WAIT(n)  asm volatile("cp.async.wait_group %0;" :: "n"(n) : "memory")
#define CP_BULK(dst, src, bytes, mbar) \
    asm volatile("cp.async.bulk.shared::cluster.global.mbarrier::complete_tx::bytes [%0], [%1], %2, [%3];" \
        :: "r"(dst), "l"(src), "r"(bytes), "r"(mbar) : "memory")
#define MBARRIER_INIT(addr, cnt) \
    asm volatile("mbarrier.init.shared.b64 [%0], %1;" :: "r"(addr), "r"(cnt) : "memory")
#define MBARRIER_ARRIVE(addr) \
    asm volatile("mbarrier.arrive.shared.b64 _, [%0];" :: "r"(addr) : "memory")
#define MBARRIER_EXPECT_TX(addr, tx) \
    asm volatile("mbarrier.arrive.expect_tx.shared.b64 _, [%0], %1;" :: "r"(addr), "r"(tx) : "memory")
#define MBARRIER_WAIT_PARITY(addr, ph) do { \
    uint32_t _m = (addr), _p = (ph), _d; \
    asm volatile("{\n\t.reg .pred p;\n\t" \
        "mbarrier.try_wait.parity.acquire.cta.shared::cta.b64 p, [%1], %2;\n\t" \
        "selp.b32 %0, 1, 0, p;\n\t}" : "=r"(_d) : "r"(_m), "r"(_p) : "memory"); \
    if (!_d) { \
        asm volatile("{\n\t.reg .pred P1;\n\tWL_%=:\n\t" \
            "mbarrier.try_wait.parity.acquire.cta.shared::cta.b64 P1, [%0], %1, 0x989680;\n\t" \
            "@P1 bra.uni WD_%=;\n\tbra.uni WL_%=;\n\tWD_%=:\n\t}" \
            :: "r"(_m), "r"(_p) : "memory"); \
    } } while (0)
#define LDMX4(r0, r1, r2, r3, addr) \
    asm volatile("ldmatrix.sync.aligned.m8n8.x4.shared.b16 {%0,%1,%2,%3}, [%4];" \
        : "=r"(r0), "=r"(r1), "=r"(r2), "=r"(r3) : "r"(addr))

__device__ __forceinline__ void mma_f16_16x8x16(
    float& c0, float& c1, float& c2, float& c3,
    uint32_t a0, uint32_t a1, uint32_t a2, uint32_t a3,
    uint32_t b0, uint32_t b1)
{
    asm volatile(
        "mma.sync.aligned.m16n8k16.row.col.f32.f16.f16.f32 "
        "{%0,%1,%2,%3}, {%4,%5,%6,%7}, {%8,%9}, {%0,%1,%2,%3};"
        : "+f"(c0), "+f"(c1), "+f"(c2), "+f"(c3)
        : "r"(a0), "r"(a1), "r"(a2), "r"(a3), "r"(b0), "r"(b1));
}

// ---------------- prep: x -> half TILED (one batch per launch) ----------------
__global__ void round_half_kernel(const float4* __restrict__ in, __half* __restrict__ out) {
    int i = blockIdx.x * 256 + threadIdx.x;
    float4 v = in[i];
    int m = i >> 9, c4 = i & 511;
    int kblk = c4 >> 3;
    int g0 = (c4 & 7) * 2;
    int r = m & 127, mblk = m >> 7;
    int phys = g0 ^ (((r >> 1) & 3) << 2);
    __half2* dst = (__half2*)(out + ((size_t)(mblk * 64 + kblk) * 4096 + r * 32 + phys * 2));
    dst[0] = __floats2half2_rn(v.x, v.y);
    dst[1] = __floats2half2_rn(v.z, v.w);
}

// ---------------- prep: W -> half TILED [n][k] ----------------
__global__ void transpose_half_kernel(const float* __restrict__ W, __half* __restrict__ WT) {
    __shared__ float t[32][132];
    int n0 = blockIdx.x * 128, kblk = blockIdx.y, k0 = kblk * 32;
    int tid = threadIdx.x;
#pragma unroll
    for (int i = 0; i < 16; i++) {
        int lin = i * 256 + tid;
        int k = lin >> 7, n = lin & 127;
        t[k][n] = W[(size_t)(k0 + k) * 2048 + n0 + n];
    }
    __syncthreads();
    int r = tid & 127;
    int cbase = (tid >> 7) * 2;
    int sw = (r >> 1) & 3;
    __half* obase = WT + (size_t)((n0 >> 7) * 64 + kblk) * 4096 + r * 32;
#pragma unroll
    for (int cc = 0; cc < 2; cc++) {
        int c = cbase + cc;
        __half h[8];
#pragma unroll
        for (int i = 0; i < 8; i++) h[i] = __float2half_rn(t[c * 8 + i][r]);
        *(uint4*)(obase + ((c ^ sw) * 8)) = *(uint4*)h;
    }
}

// ---------------- fp16 GEMM: 8-stage ring, NO __syncthreads in mainloop ----------------
#define GSTAGE_B 24576
#define NSTAGE 8
#define GEMM_SMEM (NSTAGE * GSTAGE_B + 192)

__global__ __launch_bounds__(512, 1) void gemm256_kernel(
    const __half* __restrict__ A, const __half* __restrict__ BW,
    float* __restrict__ C, __half* __restrict__ Qh, int mode)
{
    extern __shared__ __half shh[];
    uint32_t sb = smem_u32(shh);
    uint32_t mbF = sb + NSTAGE * GSTAGE_B;        // full[s]  @ +8s
    uint32_t mbE = mbF + 64;                      // empty[s] @ +8s

    int tid = threadIdx.x;
    int wid = tid >> 5, lane = tid & 31;
    int wm = wid >> 2, wn = wid & 3;
    int gq = lane >> 2, kc = lane & 3;
    int n0 = blockIdx.x * 256, m0 = blockIdx.y * 128;

    if (tid == 0) {
#pragma unroll
        for (int s = 0; s < NSTAGE; s++) {
            MBARRIER_INIT(mbF + 8 * s, 1);
            MBARRIER_INIT(mbE + 8 * s, 16);       // one arrive per warp
        }
    }
    __syncthreads();

    const __half* Ab = A  + (size_t)(m0 >> 7) * 64 * 4096;
    const __half* B0 = BW + (size_t)(n0 >> 7) * 64 * 4096;
    const __half* B1 = BW + (size_t)((n0 >> 7) + 1) * 64 * 4096;

    if (tid == 0) {
#pragma unroll
        for (int s = 0; s < NSTAGE; s++) {        // prefill all 8 stages
            MBARRIER_EXPECT_TX(mbF + 8 * s, GSTAGE_B);
            CP_BULK(sb + s * GSTAGE_B,         Ab + (size_t)s * 4096, 8192, mbF + 8 * s);
            CP_BULK(sb + s * GSTAGE_B + 8192,  B0 + (size_t)s * 4096, 8192, mbF + 8 * s);
            CP_BULK(sb + s * GSTAGE_B + 16384, B1 + (size_t)s * 4096, 8192, mbF + 8 * s);
        }
    }

    int laneAr = wm * 32 + (lane & 7) + (((lane >> 3) & 1) << 3);
    int cA = lane >> 4;
    int swA = (laneAr >> 1) & 3;
    uint32_t aAddr0 = sb + (uint32_t)laneAr * 64 + (uint32_t)((cA     ^ swA) << 4);
    uint32_t aAddr1 = sb + (uint32_t)laneAr * 64 + (uint32_t)(((2|cA) ^ swA) << 4);
    int laneBr = wn * 64 + ((lane >> 4) << 3) + (lane & 7);
    int cB = (lane >> 3) & 1;
    int swB = (laneBr >> 1) & 3;
    uint32_t bAddr0 = sb + 8192 + (uint32_t)laneBr * 64 + (uint32_t)((cB     ^ swB) << 4);
    uint32_t bAddr1 = sb + 8192 + (uint32_t)laneBr * 64 + (uint32_t)(((2|cB) ^ swB) << 4);

    float acc[2][8][4];
#pragma unroll
    for (int i = 0; i < 2; i++)
#pragma unroll
        for (int j = 0; j < 8; j++)
#pragma unroll
            for (int r = 0; r < 4; r++) acc[i][j][r] = 0.f;

    for (int kt = 0; kt < 64; kt += 4) {
#pragma unroll
        for (int u = 0; u < 4; u++) {
            int k = kt + u, s = k & (NSTAGE - 1);
            MBARRIER_WAIT_PARITY(mbF + 8 * s, (k >> 3) & 1);
            uint32_t so = (uint32_t)s * GSTAGE_B;
#pragma unroll
            for (int t = 0; t < 2; t++) {
                uint32_t aA = (t ? aAddr1 : aAddr0) + so;
                uint32_t bA = (t ? bAddr1 : bAddr0) + so;
                uint32_t af[2][4], bf[8][2];
                LDMX4(af[0][0], af[0][1], af[0][2], af[0][3], aA);
                LDMX4(af[1][0], af[1][1], af[1][2], af[1][3], aA + 1024);
#pragma unroll
                for (int nfp = 0; nfp < 4; nfp++)
                    LDMX4(bf[2 * nfp][0], bf[2 * nfp][1], bf[2 * nfp + 1][0], bf[2 * nfp + 1][1],
                          bA + nfp * 1024);
#pragma unroll
                for (int mf = 0; mf < 2; mf++)
#pragma unroll
                    for (int nf = 0; nf < 8; nf++)
                        mma_f16_16x8x16(acc[mf][nf][0], acc[mf][nf][1],
                                        acc[mf][nf][2], acc[mf][nf][3],
                                        af[mf][0], af[mf][1], af[mf][2], af[mf][3],
                                        bf[nf][0], bf[nf][1]);
            }
            if (lane == 0) MBARRIER_ARRIVE(mbE + 8 * s);   // warp done with stage s
        }
        // producer: refill the 4 stages just consumed (after ALL warps released them)
        if (tid == 0 && kt + NSTAGE < 64) {
#pragma unroll
            for (int u = 0; u < 4; u++) {
                int kl = kt + NSTAGE + u, s2 = kl & (NSTAGE - 1);
                MBARRIER_WAIT_PARITY(mbE + 8 * s2, ((kl >> 3) + 1) & 1);
                MBARRIER_EXPECT_TX(mbF + 8 * s2, GSTAGE_B);
                CP_BULK(sb + s2 * GSTAGE_B,         Ab + (size_t)kl * 4096, 8192, mbF + 8 * s2);
                CP_BULK(sb + s2 * GSTAGE_B + 8192,  B0 + (size_t)kl * 4096, 8192, mbF + 8 * s2);
                CP_BULK(sb + s2 * GSTAGE_B + 16384, B1 + (size_t)kl * 4096, 8192, mbF + 8 * s2);
            }
        }
    }

    if (mode == 0) {
#pragma unroll
        for (int mf = 0; mf < 2; mf++) {
            int r0 = m0 + wm * 32 + mf * 16 + gq;
#pragma unroll
            for (int nf = 0; nf < 8; nf++) {
                int col = n0 + wn * 64 + nf * 8 + kc * 2;
                *(float2*)&C[(size_t)r0 * 2048 + col]       = make_float2(acc[mf][nf][0], acc[mf][nf][1]);
                *(float2*)&C[(size_t)(r0 + 8) * 2048 + col] = make_float2(acc[mf][nf][2], acc[mf][nf][3]);
            }
        }
    } else {
#pragma unroll
        for (int mf = 0; mf < 2; mf++) {
            int r0 = m0 + wm * 32 + mf * 16 + gq;
            int q = r0 & 127, mblk = r0 >> 7;
            int sw = (q & 7) << 2;
#pragma unroll
            for (int nf = 0; nf < 8; nf++) {
                int col = n0 + wn * 64 + nf * 8 + kc * 2;
                int head = col >> 7, d = col & 127;
                int phys = (d >> 1) ^ sw;
                size_t base = ((size_t)(mblk * 16 + head) * 128 + q) * 128 + phys * 2;
                *(__half2*)(Qh + base)        = __floats2half2_rn(acc[mf][nf][0], acc[mf][nf][1]);
                *(__half2*)(Qh + base + 1024) = __floats2half2_rn(acc[mf][nf][2], acc[mf][nf][3]);
            }
        }
    }
}

// ---------------- sparse K/V projection -> half attn images ----------------
#define KVSTAGE_B 16384
#define KVSTAGE_H 8192
#define KV_SMEM (4 * KVSTAGE_B + 128 * 4)

__global__ __launch_bounds__(256, 1) void sparse_kv_mma_kernel(
    const int* __restrict__ anchors)
{
    extern __shared__ __half shh[];
    int* tok = (int*)(shh + 4 * KVSTAGE_H);

    int tid = threadIdx.x;
    int bh = blockIdx.x;
    int h = bh & 15, b = bh >> 4;
    int vsel = blockIdx.y;
    const __half* Bb = (vsel ? g_wvt : g_wkt) + (size_t)h * 64 * 4096;
    __half* img = (vsel ? g_vh : g_kh) + (size_t)bh * 16384;

    if (tid < 128) {
        int ti = tid >> 4;
        int tile = (ti == 7) ? 255 : anchors[(bh << 3) + ti];
        tok[tid] = tile * 16 + (tid & 15);
    }
    __syncthreads();

    int wid = tid >> 5, lane = tid & 31;
    int wm = wid >> 2, wn = wid & 3;
    int gq = lane >> 2, kc = lane & 3;

    uint32_t sb = smem_u32(shh);

    uint32_t aReg = vsel ? 8192u : 0u;
    uint32_t bReg = vsel ? 0u : 8192u;

    int laneAr = wm * 64 + (lane & 7) + (((lane >> 3) & 1) << 3);
    int cA = lane >> 4;
    int swA = (laneAr >> 1) & 3;
    uint32_t aAddr0 = sb + aReg + (uint32_t)laneAr * 64 + (uint32_t)((cA     ^ swA) << 4);
    uint32_t aAddr1 = sb + aReg + (uint32_t)laneAr * 64 + (uint32_t)(((2|cA) ^ swA) << 4);
    int laneBr = wn * 32 + ((lane >> 4) << 3) + (lane & 7);
    int cB = (lane >> 3) & 1;
    int swB = (laneBr >> 1) & 3;
    uint32_t bAddr0 = sb + bReg + (uint32_t)laneBr * 64 + (uint32_t)((cB     ^ swB) << 4);
    uint32_t bAddr1 = sb + bReg + (uint32_t)laneBr * 64 + (uint32_t)(((2|cB) ^ swB) << 4);

    float acc[4][4][4];
#pragma unroll
    for (int i = 0; i < 4; i++)
#pragma unroll
        for (int j = 0; j < 4; j++)
#pragma unroll
            for (int r = 0; r < 4; r++) acc[i][j][r] = 0.f;

#pragma unroll
    for (int s = 0; s < 3; s++) {
        uint32_t so = sb + s * KVSTAGE_B;
#pragma unroll
        for (int i = 0; i < 2; i++) {
            int cidx = i * 256 + tid;
            int rs = cidx >> 2, c = cidx & 3;
            int grow = b * SS + tok[rs];
            const __half* srcA = g_xh + (size_t)((grow >> 7) * 64 + s) * 4096
                               + (grow & 127) * 32 + ((c ^ ((grow >> 1) & 3)) * 8);
            CP_ASYNC16(so + (uint32_t)(rs * 64 + (c ^ ((rs >> 1) & 3)) * 16), srcA);
            const __half* srcB = Bb + (size_t)s * 4096 + rs * 32 + ((c ^ ((rs >> 1) & 3)) * 8);
            CP_ASYNC16(so + 8192 + (uint32_t)(rs * 64 + (c ^ ((rs >> 1) & 3)) * 16), srcB);
        }
        CP_COMMIT();
    }

    for (int kt = 0; kt < 64; kt++) {
        CP_WAIT(2);
        __syncthreads();
        if (kt + 3 < 64) {
            int sl = kt + 3;
            uint32_t so = sb + (uint32_t)(sl & 3) * KVSTAGE_B;
#pragma unroll
            for (int i = 0; i < 2; i++) {
                int cidx = i * 256 + tid;
                int rs = cidx >> 2, c = cidx & 3;
                int grow = b * SS + tok[rs];
                const __half* srcA = g_xh + (size_t)((grow >> 7) * 64 + sl) * 4096
                                   + (grow & 127) * 32 + ((c ^ ((grow >> 1) & 3)) * 8);
                CP_ASYNC16(so + (uint32_t)(rs * 64 + (c ^ ((rs >> 1) & 3)) * 16), srcA);
                const __half* srcB = Bb + (size_t)sl * 4096 + rs * 32 + ((c ^ ((rs >> 1) & 3)) * 8);
                CP_ASYNC16(so + 8192 + (uint32_t)(rs * 64 + (c ^ ((rs >> 1) & 3)) * 16), srcB);
            }
        }
        CP_COMMIT();

        uint32_t so = (uint32_t)(kt & 3) * KVSTAGE_B;
#pragma unroll
        for (int t = 0; t < 2; t++) {
            uint32_t aA = (t ? aAddr1 : aAddr0) + so;
            uint32_t bA = (t ? bAddr1 : bAddr0) + so;
            uint32_t af[4][4], bf[4][2];
#pragma unroll
            for (int mf = 0; mf < 4; mf++)
                LDMX4(af[mf][0], af[mf][1], af[mf][2], af[mf][3], aA + mf * 1024);
#pragma unroll
            for (int nfp = 0; nfp < 2; nfp++)
                LDMX4(bf[2 * nfp][0], bf[2 * nfp][1], bf[2 * nfp + 1][0], bf[2 * nfp + 1][1],
                      bA + nfp * 1024);
#pragma unroll
            for (int mf = 0; mf < 4; mf++)
#pragma unroll
                for (int nf = 0; nf < 4; nf++)
                    mma_f16_16x8x16(acc[mf][nf][0], acc[mf][nf][1],
                                    acc[mf][nf][2], acc[mf][nf][3],
                                    af[mf][0], af[mf][1], af[mf][2], af[mf][3],
                                    bf[nf][0], bf[nf][1]);
        }
    }

    {
        int sw = gq << 2;
#pragma unroll
        for (int mf = 0; mf < 4; mf++) {
            int r0 = wm * 64 + mf * 16 + gq;
            __half* row0 = img + r0 * 128;
            __half* row1 = img + (r0 + 8) * 128;
#pragma unroll
            for (int nf = 0; nf < 4; nf++) {
                int g = wn * 16 + nf * 4 + kc;
                int phys = g ^ sw;
                *(__half2*)(row0 + phys * 2) = __floats2half2_rn(acc[mf][nf][0], acc[mf][nf][1]);
                *(__half2*)(row1 + phys * 2) = __floats2half2_rn(acc[mf][nf][2], acc[mf][nf][3]);
            }
        }
    }
}

// ---------------- attention: all operands via cp.async.bulk ----------------
#define ATTN_TOK_OFF (3 * 32768)
#define ATTN_SMEM (ATTN_TOK_OFF + 512 + 16)

__global__ __launch_bounds__(256) void attn_mma_kernel(
    const int* __restrict__ anchors, __half* __restrict__ attout, int bhbase)
{
    extern __shared__ char smraw[];
    __half* QPh = ((__half*)smraw) + 2 * 16384;
    int*    tok = (int*)(smraw + ATTN_TOK_OFF);
    uint32_t sbb = smem_u32(smraw);
    uint32_t mb = sbb + ATTN_TOK_OFF + 512;

    int tid = threadIdx.x;
    int bh = bhbase + blockIdx.y;
    int b = bh >> 4, h = bh & 15;
    int q0 = blockIdx.x * 128;
    int wid = tid >> 5, lane = tid & 31;
    int gq = lane >> 2, kc = lane & 3;

    if (tid == 0) MBARRIER_INIT(mb, 1);
    if (tid < 128) {
        int ti = tid >> 4;
        int tile = (ti == 7) ? 255 : anchors[(bh << 3) + ti];
        tok[tid] = tile * 16 + (tid & 15);
    }
    __syncthreads();

    if (tid == 0) {
        const __half* qsrc = g_qh + ((size_t)((b * 32 + (q0 >> 7)) * 16 + h) * 16384);
        MBARRIER_EXPECT_TX(mb, 3 * 32768);
        CP_BULK(sbb,             g_kh + (size_t)bh * 16384, 32768, mb);
        CP_BULK(sbb + 32768,     g_vh + (size_t)bh * 16384, 32768, mb);
        CP_BULK(sbb + 2 * 32768, qsrc,                      32768, mb);
    }
    MBARRIER_WAIT_PARITY(mb, 0);

    int laneAr = wid * 16 + (lane & 7) + (((lane >> 3) & 1) << 3);
    int cA = lane >> 4;
    int laneBr = ((lane >> 4) << 3) + (lane & 7);
    int cB = (lane >> 3) & 1;
    uint32_t qBase = sbb + 2 * 32768 + (uint32_t)laneAr * 256;
    uint32_t kBase = sbb + (uint32_t)laneBr * 256;
    uint32_t vBase = sbb + 32768 + (uint32_t)laneBr * 256;
    int swAa = laneAr & 7, swBa = laneBr & 7;

    int r = wid * 16 + gq;

    float acc[16][4];
#pragma unroll
    for (int nf = 0; nf < 16; nf++)
#pragma unroll
        for (int z = 0; z < 4; z++) acc[nf][z] = 0.f;
#pragma unroll
    for (int t = 0; t < 8; t++) {
        uint32_t af[4], bf[16][2];
        LDMX4(af[0], af[1], af[2], af[3], qBase + (uint32_t)(((2 * t + cA) ^ swAa) << 4));
#pragma unroll
        for (int nfp = 0; nfp < 8; nfp++)
            LDMX4(bf[2 * nfp][0], bf[2 * nfp][1], bf[2 * nfp + 1][0], bf[2 * nfp + 1][1],
                  kBase + nfp * 4096 + (uint32_t)(((2 * t + cB) ^ swBa) << 4));
#pragma unroll
        for (int nf = 0; nf < 16; nf++)
            mma_f16_16x8x16(acc[nf][0], acc[nf][1], acc[nf][2], acc[nf][3],
                            af[0], af[1], af[2], af[3], bf[nf][0], bf[nf][1]);
    }

    {
        const float scale = 0.0883883476483184f;
        int qpos0 = q0 + r, qpos1 = qpos0 + 8;
        float mx0 = -3.0e38f, mx1 = -3.0e38f;
#pragma unroll
        for (int nf = 0; nf < 16; nf++)
#pragma unroll
            for (int j = 0; j < 2; j++) {
                int tcol = tok[nf * 8 + kc * 2 + j];
                float v0 = acc[nf][j] * scale;
                float v1 = acc[nf][2 + j] * scale;
                if (tcol > qpos0) v0 = -1e10f;
                if (tcol > qpos1) v1 = -1e10f;
                acc[nf][j] = v0; acc[nf][2 + j] = v1;
                mx0 = fmaxf(mx0, v0); mx1 = fmaxf(mx1, v1);
            }
        mx0 = fmaxf(mx0, __shfl_xor_sync(0xffffffffu, mx0, 1));
        mx0 = fmaxf(mx0, __shfl_xor_sync(0xffffffffu, mx0, 2));
        mx1 = fmaxf(mx1, __shfl_xor_sync(0xffffffffu, mx1, 1));
        mx1 = fmaxf(mx1, __shfl_xor_sync(0xffffffffu, mx1, 2));
        float s0 = 0.f, s1 = 0.f;
#pragma unroll
        for (int nf = 0; nf < 16; nf++)
#pragma unroll
            for (int j = 0; j < 2; j++) {
                float e0 = __expf(acc[nf][j] - mx0);
                float e1 = __expf(acc[nf][2 + j] - mx1);
                acc[nf][j] = e0; acc[nf][2 + j] = e1;
                s0 += e0; s1 += e1;
            }
        s0 += __shfl_xor_sync(0xffffffffu, s0, 1);
        s0 += __shfl_xor_sync(0xffffffffu, s0, 2);
        s1 += __shfl_xor_sync(0xffffffffu, s1, 1);
        s1 += __shfl_xor_sync(0xffffffffu, s1, 2);
        float inv0 = 1.f / s0, inv1 = 1.f / s1;
        int sw = (r & 7) << 2;
#pragma unroll
        for (int nf = 0; nf < 16; nf++) {
            int g = nf * 4 + kc;
            int phys = g ^ sw;
            *(__half2*)(QPh + r * 128 + phys * 2) =
                __floats2half2_rn(acc[nf][0] * inv0, acc[nf][1] * inv0);
            *(__half2*)(QPh + (r + 8) * 128 + phys * 2) =
                __floats2half2_rn(acc[nf][2] * inv1, acc[nf][3] * inv1);
        }
        __syncwarp();
    }

    float acc2[16][4];
#pragma unroll
    for (int nf = 0; nf < 16; nf++)
#pragma unroll
        for (int z = 0; z < 4; z++) acc2[nf][z] = 0.f;
#pragma unroll
    for (int t = 0; t < 8; t++) {
        uint32_t af[4], bf[16][2];
        LDMX4(af[0], af[1], af[2], af[3], qBase + (uint32_t)(((2 * t + cA) ^ swAa) << 4));
#pragma unroll
        for (int nfp = 0; nfp < 8; nfp++)
            LDMX4(bf[2 * nfp][0], bf[2 * nfp][1], bf[2 * nfp + 1][0], bf[2 * nfp + 1][1],
                  vBase + nfp * 4096 + (uint32_t)(((2 * t + cB) ^ swBa) << 4));
#pragma unroll
        for (int nf = 0; nf < 16; nf++)
            mma_f16_16x8x16(acc2[nf][0], acc2[nf][1], acc2[nf][2], acc2[nf][3],
                            af[0], af[1], af[2], af[3], bf[nf][0], bf[nf][1]);
    }

    {
        int mblk = (b * SS + q0) >> 7;
        __half* abase = attout + (size_t)mblk * 64 * 4096;
        int sw = ((r >> 1) & 3) << 2;
#pragma unroll
        for (int nf = 0; nf < 16; nf++) {
            int col = h * HDIM + nf * 8 + kc * 2;
            int kblk = col >> 5, kcol = col & 31;
            int phys = (kcol >> 1) ^ sw;
            *(__half2*)(abase + (size_t)kblk * 4096 + r * 32 + phys * 2) =
                __floats2half2_rn(acc2[nf][0], acc2[nf][1]);
            *(__half2*)(abase + (size_t)kblk * 4096 + (r + 8) * 32 + phys * 2) =
                __floats2half2_rn(acc2[nf][2], acc2[nf][3]);
        }
    }
}

// ---------------- streams/events ----------------
static cudaStream_t g_s1a, g_s1b, g_s2, g_s3;
static cudaEvent_t g_estart, g_erhb[4], g_ewq, g_ewo, g_ekv, g_e1[4], g_e2[4], g_e3;
static bool g_streams_ok = [](){
    cudaStreamCreateWithFlags(&g_s1a, cudaStreamNonBlocking);
    cudaStreamCreateWithFlags(&g_s1b, cudaStreamNonBlocking);
    cudaStreamCreateWithFlags(&g_s2,  cudaStreamNonBlocking);
    cudaStreamCreateWithFlags(&g_s3,  cudaStreamNonBlocking);
    cudaEventCreateWithFlags(&g_estart, cudaEventDisableTiming);
    cudaEventCreateWithFlags(&g_ewq, cudaEventDisableTiming);
    cudaEventCreateWithFlags(&g_ewo, cudaEventDisableTiming);
    cudaEventCreateWithFlags(&g_ekv, cudaEventDisableTiming);
    cudaEventCreateWithFlags(&g_e3,  cudaEventDisableTiming);
    for (int i = 0; i < 4; i++) {
        cudaEventCreateWithFlags(&g_erhb[i], cudaEventDisableTiming);
        cudaEventCreateWithFlags(&g_e1[i], cudaEventDisableTiming);
        cudaEventCreateWithFlags(&g_e2[i], cudaEventDisableTiming);
    }
    return true;
}();

// ---------------- launch ----------------
extern "C" void kernel_launch(void* const* d_in, const int* in_sizes, int n_in,
                              void* d_out, int out_size)
{
    const float* x       = (const float*)d_in[0];
    const int*   anchors = (const int*)  d_in[1];
    const float* Wq      = (const float*)d_in[2];
    const float* Wk      = (const float*)d_in[3];
    const float* Wv      = (const float*)d_in[4];
    const float* Wo      = (const float*)d_in[5];
    float* out = (float*)d_out;

    __half *qhp, *attp, *xhp, *wqtp, *wotp, *wktp, *wvtp;
    cudaGetSymbolAddress((void**)&qhp,  g_qh);
    cudaGetSymbolAddress((void**)&attp, g_att);
    cudaGetSymbolAddress((void**)&xhp,  g_xh);
    cudaGetSymbolAddress((void**)&wqtp, g_wqt);
    cudaGetSymbolAddress((void**)&wotp, g_wot);
    cudaGetSymbolAddress((void**)&wktp, g_wkt);
    cudaGetSymbolAddress((void**)&wvtp, g_wvt);

    cudaFuncSetAttribute(attn_mma_kernel, cudaFuncAttributeMaxDynamicSharedMemorySize, ATTN_SMEM);
    cudaFuncSetAttribute(gemm256_kernel, cudaFuncAttributeMaxDynamicSharedMemorySize, GEMM_SMEM);
    cudaFuncSetAttribute(sparse_kv_mma_kernel, cudaFuncAttributeMaxDynamicSharedMemorySize, KV_SMEM);

    const size_t ABLK = (size_t)SS * DD;
    const size_t X4BLK = (size_t)SS * DD / 4;

    // FORK root
    cudaEventRecord(g_estart, 0);

    for (int b = 0; b < 4; b++) {
        round_half_kernel<<<(SS * DD / 4) / 256, 256>>>(
            (const float4*)(x + b * 4 * X4BLK), xhp + b * ABLK);
        cudaEventRecord(g_erhb[b], 0);
    }

    cudaStreamWaitEvent(g_s2, g_estart, 0);
    transpose_half_kernel<<<dim3(16, 64), 256, 0, g_s2>>>(Wq, wqtp);
    cudaEventRecord(g_ewq, g_s2);
    transpose_half_kernel<<<dim3(16, 64), 256, 0, g_s2>>>(Wk, wktp);
    transpose_half_kernel<<<dim3(16, 64), 256, 0, g_s2>>>(Wv, wvtp);
    transpose_half_kernel<<<dim3(16, 64), 256, 0, g_s2>>>(Wo, wotp);
    cudaEventRecord(g_ewo, g_s2);
    cudaStreamWaitEvent(g_s2, g_erhb[3], 0);
    sparse_kv_mma_kernel<<<dim3(64, 2), 256, KV_SMEM, g_s2>>>(anchors);
    cudaEventRecord(g_ekv, g_s2);

    for (int b = 0; b < 4; b++) {
        cudaStream_t st = (b & 1) ? g_s1b : g_s1a;
        cudaStreamWaitEvent(st, g_erhb[b], 0);
        cudaStreamWaitEvent(st, g_ewq, 0);
        gemm256_kernel<<<dim3(8, 32), 512, GEMM_SMEM, st>>>(
            xhp + b * ABLK, wqtp, nullptr, qhp + b * ABLK, 1);
        cudaEventRecord(g_e1[b], st);
    }
    for (int b = 0; b < 4; b++) {
        cudaStreamWaitEvent(g_s2, g_e1[b], 0);
        attn_mma_kernel<<<dim3(32, 16), 256, ATTN_SMEM, g_s2>>>(anchors, attp, b * 16);
        cudaEventRecord(g_e2[b], g_s2);
    }
    cudaStreamWaitEvent(0, g_ewo, 0);
    cudaStreamWaitEvent(g_s3, g_ewo, 0);
    for (int b = 0; b < 4; b++) {
        cudaStream_t st = (b & 1) ? g_s3 : (cudaStream_t)0;
        cudaStreamWaitEvent(st, g_e2[b], 0);
        gemm256_kernel<<<dim3(8, 32), 512, GEMM_SMEM, st>>>(
            attp + b * ABLK, wotp, out + b * ABLK, nullptr, 0);
    }
    cudaEventRecord(g_e3, g_s3);
    cudaStreamWaitEvent(0, g_e3, 0);
}